// round 3
// baseline (speedup 1.0000x reference)
#include <cuda_runtime.h>

#define NB 2048
#define NT 256

// Per-block partial sums (device globals: no allocation allowed)
__device__ float g_part_b[NB];
__device__ float g_part_p[NB];
__device__ float g_part_d[NB];

// Shapes: outputs (2,3,256,256,64), targets (2,4,256,256,64)
#define SPATIAL (256 * 256 * 64)          // 4194304 = 2^22
#define NTOT    (2 * SPATIAL)             // 8388608 = 2^23
#define XSTRIDE (256 * 64)                // 16384
#define YSTRIDE 64

__global__ __launch_bounds__(NT) void loss_kernel(
    const float* __restrict__ outp, const float* __restrict__ tgt)
{
    const float EPS = 1e-10f;
    const float DXc = 0.1f, DYc = 0.1f;
    const float SIXTH = 1.0f / 6.0f;

    float sb = 0.f, sp = 0.f, sd = 0.f;

    for (int idx = blockIdx.x * NT + threadIdx.x; idx < NTOT; idx += NB * NT) {
        const int b    = idx >> 22;
        const int sidx = idx & (SPATIAL - 1);
        const int z    = sidx & 63;
        const int y    = (sidx >> 6) & 255;
        const int x    = sidx >> 14;

        const float* po = outp + (size_t)b * 3 * SPATIAL + sidx;   // bx_p
        const float* pt = tgt  + (size_t)b * 4 * SPATIAL + sidx;   // bx_t

        // ---- pointwise losses ----
        const float bxp = po[0], byp = po[SPATIAL], bzp = po[2 * SPATIAL];
        const float bxt = pt[0], byt = pt[SPATIAL], bzt = pt[2 * SPATIAL];
        const float bxt2 = bxt * bxt, byt2 = byt * byt, bzt2 = bzt * bzt;

        const float t1 = bxp * bxp + byp * byp - bxt2 - byt2;
        sb += t1 * t1 / (bxt2 + byt2 + EPS);
        const float dz = bzp - bzt;
        const float dz2 = dz * dz;
        sb += dz2 * dz2 / (bzt2 + EPS);

        const float cr = bxp * byt - byp * bxt;
        sp += cr * cr / (bxt2 + byt2 + bzt2 + EPS);

        // ---- divergence flux loss (cell-centered; valid cells only) ----
        if (x < 255 && y < 255 && z < 63) {
            // corner c encodes (i,j,k) as i*4 + j*2 + k; offset = i*XSTRIDE + j*YSTRIDE + k
            float bx[8], by[8], bz[8], zz[8];
            const float* pz = pt + 3 * SPATIAL;
            #pragma unroll
            for (int c = 0; c < 8; c++) {
                const int off = ((c >> 2) & 1) * XSTRIDE + ((c >> 1) & 1) * YSTRIDE + (c & 1);
                bx[c] = po[off];
                by[c] = po[SPATIAL + off];
                bz[c] = po[2 * SPATIAL + off];
                zz[c] = pz[off];
            }

            float num =
                  0.25f * (bx[4] + bx[6] + bx[5] + bx[7]) * DYc * 0.5f * (zz[5] - zz[4] + zz[7] - zz[6])
                - 0.25f * (bx[0] + bx[2] + bx[1] + bx[3]) * DYc * 0.5f * (zz[1] - zz[0] + zz[3] - zz[2])
                + 0.25f * (by[2] + by[6] + by[3] + by[7]) * DXc * 0.5f * (zz[3] - zz[2] + zz[7] - zz[6])
                - 0.25f * (by[0] + by[4] + by[1] + by[5]) * DXc * 0.5f * (zz[1] - zz[0] + zz[5] - zz[4])
                + 0.25f * (bz[1] + bz[3] + bz[5] + bz[7]) * DXc * DYc
                - 0.25f * (bz[0] + bz[2] + bz[4] + bz[6]) * DXc * DYc
                + (bx[1] + bx[5] + bx[7]) * DYc * (zz[1] - zz[5]) * SIXTH
                + (bx[3] + bx[7] + bx[5]) * DYc * (zz[3] - zz[7]) * SIXTH
                + (by[5] + by[7] + by[3]) * DXc * (zz[5] - zz[7]) * SIXTH
                + (by[1] + by[3] + by[7]) * DXc * (zz[1] - zz[3]) * SIXTH
                - (bx[0] + bx[4] + bx[6]) * DYc * (zz[0] - zz[4]) * SIXTH
                - (bx[2] + bx[6] + bx[4]) * DYc * (zz[2] - zz[6]) * SIXTH
                - (by[4] + by[6] + by[2]) * DXc * (zz[4] - zz[6]) * SIXTH
                - (by[0] + by[2] + by[6]) * DXc * (zz[0] - zz[2]) * SIXTH;

            const float bxc = 0.125f * (bx[0] + bx[1] + bx[2] + bx[3] + bx[4] + bx[5] + bx[6] + bx[7]);
            const float byc = 0.125f * (by[0] + by[1] + by[2] + by[3] + by[4] + by[5] + by[6] + by[7]);
            const float bzc = 0.125f * (bz[0] + bz[1] + bz[2] + bz[3] + bz[4] + bz[5] + bz[6] + bz[7]);
            const float den = bxc * bxc + byc * byc + bzc * bzc + EPS;
            sd += num * num / den;
        }
    }

    // ---- block reduction (deterministic tree) ----
    __shared__ float shb[NT], shp[NT], shd[NT];
    shb[threadIdx.x] = sb;
    shp[threadIdx.x] = sp;
    shd[threadIdx.x] = sd;
    __syncthreads();
    for (int s = NT / 2; s > 0; s >>= 1) {
        if (threadIdx.x < s) {
            shb[threadIdx.x] += shb[threadIdx.x + s];
            shp[threadIdx.x] += shp[threadIdx.x + s];
            shd[threadIdx.x] += shd[threadIdx.x + s];
        }
        __syncthreads();
    }
    if (threadIdx.x == 0) {
        g_part_b[blockIdx.x] = shb[0];
        g_part_p[blockIdx.x] = shp[0];
        g_part_d[blockIdx.x] = shd[0];
    }
}

__global__ __launch_bounds__(NT) void reduce_kernel(float* __restrict__ out)
{
    __shared__ double rb[NT], rp[NT], rd[NT];
    double b = 0.0, p = 0.0, d = 0.0;
    for (int i = threadIdx.x; i < NB; i += NT) {
        b += (double)g_part_b[i];
        p += (double)g_part_p[i];
        d += (double)g_part_d[i];
    }
    rb[threadIdx.x] = b; rp[threadIdx.x] = p; rd[threadIdx.x] = d;
    __syncthreads();
    for (int s = NT / 2; s > 0; s >>= 1) {
        if (threadIdx.x < s) {
            rb[threadIdx.x] += rb[threadIdx.x + s];
            rp[threadIdx.x] += rp[threadIdx.x + s];
            rd[threadIdx.x] += rd[threadIdx.x + s];
        }
        __syncthreads();
    }
    if (threadIdx.x == 0) {
        const double N  = 8388608.0;           // 2*256*256*64
        const double M  = 8193150.0;           // 2*255*255*63
        const double loss_b   = rb[0] / N;
        const double loss_p   = rp[0] / N;
        const double loss_div = rd[0] / M * 1.0e4;   // / DX^2 / DY^2
        out[0] = (float)(1000.0 * loss_b + 1000.0 * loss_p);
        out[1] = (float)(100.0 * loss_div);
    }
}

extern "C" void kernel_launch(void* const* d_in, const int* in_sizes, int n_in,
                              void* d_out, int out_size)
{
    const float* outputs = (const float*)d_in[0];
    const float* targets = (const float*)d_in[1];
    float* out = (float*)d_out;

    loss_kernel<<<NB, NT>>>(outputs, targets);
    reduce_kernel<<<1, NT>>>(out);
}